// round 3
// baseline (speedup 1.0000x reference)
#include <cuda_runtime.h>

// ---------------------------------------------------------------------------
// WavePlaneField: 6 planes reconstructed via 2-level inverse DWT (coif4,
// periodization), bilinear-sampled at N points, channelwise product.
//
// Phase 1 (4 kernels): separable inverse DWT per plane into g_planes[H,W,C].
// Phase 2 (1 kernel): warp-per-point sampler, lane = channel.
// ---------------------------------------------------------------------------

#define CCH 32

// All planes have H=256. W per plane:
__constant__ int c_W[6]    = {256, 256, 64, 256, 64, 64};
__constant__ int c_POFF[6] = {0, 65536, 131072, 147456, 212992, 229376}; // pixel offsets

// coif4 reconstruction filters (24 taps)
__constant__ float REC_LO_C[24] = {
    0.0008923136685823146f, -0.0016294920126017326f, -0.0073461663276420935f,
    0.016068943964776348f, 0.026682300156053072f, -0.08126669968087875f,
    -0.05607731331675481f, 0.41530840703043026f, 0.782238930920499f,
    0.4343860564914685f, -0.06662747426342504f, -0.09622044203398798f,
    0.03933442712333749f, 0.025082261844864097f, -0.015211731527946259f,
    -0.00565828668661072f, 0.003751436157278457f, 0.0012665619292989445f,
    -0.0005890207562443383f, -0.00025997455248771324f, 6.233903446100713e-05f,
    3.1229875865345646e-05f, -3.2596802368833675e-06f, -1.7849850030882614e-06f
};
__constant__ float REC_HI_C[24] = {
    -1.7849850030882614e-06f, 3.2596802368833675e-06f, 3.1229875865345646e-05f,
    -6.233903446100713e-05f, -0.00025997455248771324f, 0.0005890207562443383f,
    0.0012665619292989445f, -0.003751436157278457f, -0.00565828668661072f,
    0.015211731527946259f, 0.025082261844864097f, -0.03933442712333749f,
    -0.09622044203398798f, 0.06662747426342504f, 0.4343860564914685f,
    -0.782238930920499f, 0.41530840703043026f, 0.05607731331675481f,
    -0.08126669968087875f, -0.026682300156053072f, 0.016068943964776348f,
    0.0073461663276420935f, -0.0016294920126017326f, -0.0008923136685823146f
};

// Scratch (static device globals; per-plane strides sized for the largest plane)
#define S_LO1 262144    // C*128*64
#define S_MID 524288    // C*128*128
#define S_LO2 1048576   // C*256*128
__device__ float g_lo1[6 * S_LO1];
__device__ float g_hi1[6 * S_LO1];
__device__ float g_mid[6 * S_MID];
__device__ float g_lo2[6 * S_LO2];
__device__ float g_hi2[6 * S_LO2];
__device__ float g_planes[245760 * CCH];   // [H,W,C] per plane, concat

struct CoefPtrs {
    const float* yl[6];
    const float* yha[6];
    const float* yhb[6];
};

// Stage 1: level-1 H-axis synthesis. in: yl[C,64,w4], yhb[C,3,64,w4]
// out: lo1,hi1 [C,128,w4]
__global__ void k_stage1(CoefPtrs P) {
    const int pl = blockIdx.y;
    const int w4 = c_W[pl] >> 2;
    const int n = CCH * 128 * w4;
    const int tid = blockIdx.x * blockDim.x + threadIdx.x;
    if (tid >= n) return;
    const int x = tid % w4;
    const int i = (tid / w4) & 127;
    const int c = tid / (w4 * 128);
    const int s = i >> 1, p = i & 1;
    const float* yl = P.yl[pl];
    const float* yhb = P.yhb[pl];
    const int bandStride = 64 * w4;
    float lo = 0.f, hi = 0.f;
#pragma unroll
    for (int m = 0; m < 12; m++) {
        int row = s - m; if (row < 0) row += 64;
        const float fl = REC_LO_C[2 * m + p];
        const float fh = REC_HI_C[2 * m + p];
        const int bi = (c * 64 + row) * w4 + x;
        const int b0 = ((c * 3 + 0) * 64 + row) * w4 + x;
        lo += fl * yl[bi] + fh * yhb[b0];
        hi += fl * yhb[b0 + bandStride] + fh * yhb[b0 + 2 * bandStride];
    }
    g_lo1[pl * S_LO1 + tid] = lo;
    g_hi1[pl * S_LO1 + tid] = hi;
}

// Stage 2: level-1 W-axis synthesis. in: lo1,hi1 [C,128,w4] -> mid [C,128,w2]
__global__ void k_stage2() {
    const int pl = blockIdx.y;
    const int w2 = c_W[pl] >> 1;
    const int w4 = w2 >> 1;
    const int n = CCH * 128 * w2;
    const int tid = blockIdx.x * blockDim.x + threadIdx.x;
    if (tid >= n) return;
    const int j = tid % w2;
    const int i = (tid / w2) & 127;
    const int c = tid / (w2 * 128);
    const int s = j >> 1, p = j & 1;
    const int base = pl * S_LO1 + (c * 128 + i) * w4;
    float v = 0.f;
#pragma unroll
    for (int m = 0; m < 12; m++) {
        int col = s - m; if (col < 0) col += w4;
        v += REC_LO_C[2 * m + p] * g_lo1[base + col]
           + REC_HI_C[2 * m + p] * g_hi1[base + col];
    }
    g_mid[pl * S_MID + tid] = v;
}

// Stage 3: level-2 H-axis synthesis. in: mid [C,128,w2], yha [C,3,128,w2]
// out: lo2,hi2 [C,256,w2]
__global__ void k_stage3(CoefPtrs P) {
    const int pl = blockIdx.y;
    const int w2 = c_W[pl] >> 1;
    const int n = CCH * 256 * w2;
    const int tid = blockIdx.x * blockDim.x + threadIdx.x;
    if (tid >= n) return;
    const int x = tid % w2;
    const int i = (tid / w2) & 255;
    const int c = tid / (w2 * 256);
    const int s = i >> 1, p = i & 1;
    const float* yha = P.yha[pl];
    const int bandStride = 128 * w2;
    const int midBase = pl * S_MID;
    float lo = 0.f, hi = 0.f;
#pragma unroll
    for (int m = 0; m < 12; m++) {
        int row = s - m; if (row < 0) row += 128;
        const float fl = REC_LO_C[2 * m + p];
        const float fh = REC_HI_C[2 * m + p];
        const int bi = (c * 128 + row) * w2 + x;
        const int b0 = ((c * 3 + 0) * 128 + row) * w2 + x;
        lo += fl * g_mid[midBase + bi] + fh * yha[b0];
        hi += fl * yha[b0 + bandStride] + fh * yha[b0 + 2 * bandStride];
    }
    g_lo2[pl * S_LO2 + tid] = lo;
    g_hi2[pl * S_LO2 + tid] = hi;
}

// Stage 4: level-2 W-axis synthesis + transpose to [H,W,C].
// in: lo2,hi2 [C,256,w2] -> g_planes[(poff + y*W + x)*32 + c]
__global__ void k_stage4() {
    const int pl = blockIdx.y;
    const int W = c_W[pl];
    const int w2 = W >> 1;
    const int n = 256 * W * CCH;
    const int tid = blockIdx.x * blockDim.x + threadIdx.x;
    if (tid >= n) return;
    const int c = tid & 31;
    const int x = (tid >> 5) % W;
    const int y = tid / (32 * W);
    const int s = x >> 1, p = x & 1;
    const int base = pl * S_LO2 + (c * 256 + y) * w2;
    float v = 0.f;
#pragma unroll
    for (int m = 0; m < 12; m++) {
        int col = s - m; if (col < 0) col += w2;
        v += REC_LO_C[2 * m + p] * g_lo2[base + col]
           + REC_HI_C[2 * m + p] * g_hi2[base + col];
    }
    g_planes[((size_t)(c_POFF[pl] + y * W + x)) * CCH + c] = v;
}

// Phase 2: warp per point, lane = channel.
__global__ void __launch_bounds__(256) k_sample(const float* __restrict__ pts,
                                                const float* __restrict__ ts,
                                                float* __restrict__ out,
                                                int nPts) {
    const int warp = (blockIdx.x * blockDim.x + threadIdx.x) >> 5;
    const int lane = threadIdx.x & 31;
    if (warp >= nPts) return;

    const float px = pts[warp * 3 + 0];
    const float py = pts[warp * 3 + 1];
    const float pz = pts[warp * 3 + 2];
    const float tt = ts[warp];
    // pts_n = (pts - B)*(2/(-2B)) - 1 = -pts/B
    const float inv = -1.0f / 1.3f;
    float p4[4];
    p4[0] = px * inv;
    p4[1] = py * inv;
    p4[2] = pz * inv;
    p4[3] = tt * 2.0f - 1.0f;

    constexpr int QIDX[6] = {0, 0, 3, 1, 3, 3};
    constexpr int RIDX[6] = {1, 2, 0, 2, 1, 2};
    constexpr int PW[6]   = {256, 256, 64, 256, 64, 64};
    constexpr int POFF[6] = {0, 65536, 131072, 147456, 212992, 229376};

    float prod = 1.0f;
#pragma unroll
    for (int ii = 0; ii < 6; ii++) {
        const int W = PW[ii];
        const float cx = p4[QIDX[ii]];
        const float cy = p4[RIDX[ii]];
        float xf = fminf(fmaxf((cx + 1.0f) * 0.5f * (float)(W - 1), 0.0f), (float)(W - 1));
        float yf = fminf(fmaxf((cy + 1.0f) * 0.5f * 255.0f, 0.0f), 255.0f);
        float x0f = fminf(fmaxf(floorf(xf), 0.0f), (float)(W - 2));
        float y0f = fminf(fmaxf(floorf(yf), 0.0f), 254.0f);
        const float wx = xf - x0f;
        const float wy = yf - y0f;
        const int x0 = (int)x0f;
        const int y0 = (int)y0f;
        const float* pl = g_planes + (size_t)POFF[ii] * CCH;
        const int i00 = (y0 * W + x0) * CCH + lane;
        const float v00 = pl[i00];
        const float v01 = pl[i00 + CCH];
        const float v10 = pl[i00 + W * CCH];
        const float v11 = pl[i00 + W * CCH + CCH];
        const float v = v00 * (1.0f - wy) * (1.0f - wx)
                      + v01 * (1.0f - wy) * wx
                      + v10 * wy * (1.0f - wx)
                      + v11 * wy * wx;
        prod *= v;
    }
    out[(size_t)warp * CCH + lane] = prod;
}

extern "C" void kernel_launch(void* const* d_in, const int* in_sizes, int n_in,
                              void* d_out, int out_size) {
    const float* pts = (const float*)d_in[0];
    const float* ts  = (const float*)d_in[1];
    CoefPtrs P;
    for (int i = 0; i < 6; i++) {
        P.yl[i]  = (const float*)d_in[2 + 3 * i];
        P.yha[i] = (const float*)d_in[3 + 3 * i];
        P.yhb[i] = (const float*)d_in[4 + 3 * i];
    }
    float* out = (float*)d_out;
    const int nPts = in_sizes[1];   // timestamps count = N

    dim3 blk(256);
    k_stage1<<<dim3((CCH * 128 * 64 + 255) / 256, 6), blk>>>(P);
    k_stage2<<<dim3((CCH * 128 * 128 + 255) / 256, 6), blk>>>();
    k_stage3<<<dim3((CCH * 256 * 128 + 255) / 256, 6), blk>>>(P);
    k_stage4<<<dim3((256 * 256 * CCH + 255) / 256, 6), blk>>>();

    const int totalThreads = nPts * 32;
    k_sample<<<(totalThreads + 255) / 256, 256>>>(pts, ts, out, nPts);
}

// round 5
// speedup vs baseline: 3.2808x; 3.2808x over previous
#include <cuda_runtime.h>

// ---------------------------------------------------------------------------
// WavePlaneField: 6 planes reconstructed via 2-level inverse DWT (coif4,
// periodization), bilinear-sampled at N points, channelwise product.
//
// Phase 1 (4 kernels): separable inverse DWT per plane into g_planes[H,W,C].
//   Stage 4 is row-tiled through shared memory (R3 fix: the old version did
//   32-way scattered gathers, L1tex 97.9% saturated).
// Phase 2 (1 kernel): warp-per-point sampler, lane = channel.
// ---------------------------------------------------------------------------

#define CCH 32

// All planes have H=256. W per plane:
__constant__ int c_W[6]    = {256, 256, 64, 256, 64, 64};
__constant__ int c_POFF[6] = {0, 65536, 131072, 147456, 212992, 229376}; // pixel offsets

// coif4 reconstruction filters (24 taps)
__constant__ float REC_LO_C[24] = {
    0.0008923136685823146f, -0.0016294920126017326f, -0.0073461663276420935f,
    0.016068943964776348f, 0.026682300156053072f, -0.08126669968087875f,
    -0.05607731331675481f, 0.41530840703043026f, 0.782238930920499f,
    0.4343860564914685f, -0.06662747426342504f, -0.09622044203398798f,
    0.03933442712333749f, 0.025082261844864097f, -0.015211731527946259f,
    -0.00565828668661072f, 0.003751436157278457f, 0.0012665619292989445f,
    -0.0005890207562443383f, -0.00025997455248771324f, 6.233903446100713e-05f,
    3.1229875865345646e-05f, -3.2596802368833675e-06f, -1.7849850030882614e-06f
};
__constant__ float REC_HI_C[24] = {
    -1.7849850030882614e-06f, 3.2596802368833675e-06f, 3.1229875865345646e-05f,
    -6.233903446100713e-05f, -0.00025997455248771324f, 0.0005890207562443383f,
    0.0012665619292989445f, -0.003751436157278457f, -0.00565828668661072f,
    0.015211731527946259f, 0.025082261844864097f, -0.03933442712333749f,
    -0.09622044203398798f, 0.06662747426342504f, 0.4343860564914685f,
    -0.782238930920499f, 0.41530840703043026f, 0.05607731331675481f,
    -0.08126669968087875f, -0.026682300156053072f, 0.016068943964776348f,
    0.0073461663276420935f, -0.0016294920126017326f, -0.0008923136685823146f
};

// Scratch (static device globals; per-plane strides sized for the largest plane)
#define S_LO1 262144    // C*128*64
#define S_MID 524288    // C*128*128
#define S_LO2 1048576   // C*256*128
__device__ float g_lo1[6 * S_LO1];
__device__ float g_hi1[6 * S_LO1];
__device__ float g_mid[6 * S_MID];
__device__ float g_lo2[6 * S_LO2];
__device__ float g_hi2[6 * S_LO2];
__device__ float g_planes[245760 * CCH];   // [H,W,C] per plane, concat

struct CoefPtrs {
    const float* yl[6];
    const float* yha[6];
    const float* yhb[6];
};

// Stage 1: level-1 H-axis synthesis. in: yl[C,64,w4], yhb[C,3,64,w4]
// out: lo1,hi1 [C,128,w4]
__global__ void k_stage1(CoefPtrs P) {
    const int pl = blockIdx.y;
    const int w4 = c_W[pl] >> 2;
    const int n = CCH * 128 * w4;
    const int tid = blockIdx.x * blockDim.x + threadIdx.x;
    if (tid >= n) return;
    const int x = tid % w4;
    const int i = (tid / w4) & 127;
    const int c = tid / (w4 * 128);
    const int s = i >> 1, p = i & 1;
    const float* yl = P.yl[pl];
    const float* yhb = P.yhb[pl];
    const int bandStride = 64 * w4;
    float lo = 0.f, hi = 0.f;
#pragma unroll
    for (int m = 0; m < 12; m++) {
        int row = s - m; if (row < 0) row += 64;
        const float fl = REC_LO_C[2 * m + p];
        const float fh = REC_HI_C[2 * m + p];
        const int bi = (c * 64 + row) * w4 + x;
        const int b0 = ((c * 3 + 0) * 64 + row) * w4 + x;
        lo += fl * yl[bi] + fh * yhb[b0];
        hi += fl * yhb[b0 + bandStride] + fh * yhb[b0 + 2 * bandStride];
    }
    g_lo1[pl * S_LO1 + tid] = lo;
    g_hi1[pl * S_LO1 + tid] = hi;
}

// Stage 2: level-1 W-axis synthesis. in: lo1,hi1 [C,128,w4] -> mid [C,128,w2]
__global__ void k_stage2() {
    const int pl = blockIdx.y;
    const int w2 = c_W[pl] >> 1;
    const int w4 = w2 >> 1;
    const int n = CCH * 128 * w2;
    const int tid = blockIdx.x * blockDim.x + threadIdx.x;
    if (tid >= n) return;
    const int j = tid % w2;
    const int i = (tid / w2) & 127;
    const int c = tid / (w2 * 128);
    const int s = j >> 1, p = j & 1;
    const int base = pl * S_LO1 + (c * 128 + i) * w4;
    float v = 0.f;
#pragma unroll
    for (int m = 0; m < 12; m++) {
        int col = s - m; if (col < 0) col += w4;
        v += REC_LO_C[2 * m + p] * g_lo1[base + col]
           + REC_HI_C[2 * m + p] * g_hi1[base + col];
    }
    g_mid[pl * S_MID + tid] = v;
}

// Stage 3: level-2 H-axis synthesis. in: mid [C,128,w2], yha [C,3,128,w2]
// out: lo2,hi2 [C,256,w2]
__global__ void k_stage3(CoefPtrs P) {
    const int pl = blockIdx.y;
    const int w2 = c_W[pl] >> 1;
    const int n = CCH * 256 * w2;
    const int tid = blockIdx.x * blockDim.x + threadIdx.x;
    if (tid >= n) return;
    const int x = tid % w2;
    const int i = (tid / w2) & 255;
    const int c = tid / (w2 * 256);
    const int s = i >> 1, p = i & 1;
    const float* yha = P.yha[pl];
    const int bandStride = 128 * w2;
    const int midBase = pl * S_MID;
    float lo = 0.f, hi = 0.f;
#pragma unroll
    for (int m = 0; m < 12; m++) {
        int row = s - m; if (row < 0) row += 128;
        const float fl = REC_LO_C[2 * m + p];
        const float fh = REC_HI_C[2 * m + p];
        const int bi = (c * 128 + row) * w2 + x;
        const int b0 = ((c * 3 + 0) * 128 + row) * w2 + x;
        lo += fl * g_mid[midBase + bi] + fh * yha[b0];
        hi += fl * yha[b0 + bandStride] + fh * yha[b0 + 2 * bandStride];
    }
    g_lo2[pl * S_LO2 + tid] = lo;
    g_hi2[pl * S_LO2 + tid] = hi;
}

// Stage 4 (row-tiled): level-2 W-axis synthesis + transpose to [H,W,C].
// One block per (plane, y). Cooperative coalesced load of the 32-channel
// lo2/hi2 rows into padded smem (stride 129 -> conflict-free lane=c reads),
// then compute W*32 outputs with fully coalesced writes.
__global__ void __launch_bounds__(256) k_stage4() {
    const int pl = blockIdx.y;
    const int W = c_W[pl];
    const int w2 = W >> 1;
    const int y = blockIdx.x;

    __shared__ float lo_s[32][129];
    __shared__ float hi_s[32][129];

    const int sh = (w2 == 128) ? 7 : 5;          // log2(w2)
    const int rowBase = pl * S_LO2 + y * w2;     // + c*256*w2 per channel
    for (int t = threadIdx.x; t < 32 * w2; t += 256) {
        const int c = t >> sh;
        const int col = t & (w2 - 1);
        const int gi = rowBase + c * (256 * w2) + col;
        lo_s[c][col] = g_lo2[gi];
        hi_s[c][col] = g_hi2[gi];
    }
    __syncthreads();

    float* __restrict__ outRow = g_planes + ((size_t)(c_POFF[pl] + y * W)) * CCH;
    const int n = W * CCH;
    for (int t = threadIdx.x; t < n; t += 256) {
        const int c = t & 31;                     // = lane
        const int x = t >> 5;
        const int s = x >> 1, p = x & 1;
        float v = 0.f;
#pragma unroll
        for (int m = 0; m < 12; m++) {
            int col = s - m; if (col < 0) col += w2;
            v += REC_LO_C[2 * m + p] * lo_s[c][col]
               + REC_HI_C[2 * m + p] * hi_s[c][col];
        }
        outRow[t] = v;
    }
}

// Phase 2: warp per point, lane = channel.
__global__ void __launch_bounds__(256) k_sample(const float* __restrict__ pts,
                                                const float* __restrict__ ts,
                                                float* __restrict__ out,
                                                int nPts) {
    const int warp = (blockIdx.x * blockDim.x + threadIdx.x) >> 5;
    const int lane = threadIdx.x & 31;
    if (warp >= nPts) return;

    const float px = pts[warp * 3 + 0];
    const float py = pts[warp * 3 + 1];
    const float pz = pts[warp * 3 + 2];
    const float tt = ts[warp];
    // pts_n = (pts - B)*(2/(-2B)) - 1 = -pts/B
    const float inv = -1.0f / 1.3f;
    float p4[4];
    p4[0] = px * inv;
    p4[1] = py * inv;
    p4[2] = pz * inv;
    p4[3] = tt * 2.0f - 1.0f;

    constexpr int QIDX[6] = {0, 0, 3, 1, 3, 3};
    constexpr int RIDX[6] = {1, 2, 0, 2, 1, 2};
    constexpr int PW[6]   = {256, 256, 64, 256, 64, 64};
    constexpr int POFF[6] = {0, 65536, 131072, 147456, 212992, 229376};

    float prod = 1.0f;
#pragma unroll
    for (int ii = 0; ii < 6; ii++) {
        const int W = PW[ii];
        const float cx = p4[QIDX[ii]];
        const float cy = p4[RIDX[ii]];
        float xf = fminf(fmaxf((cx + 1.0f) * 0.5f * (float)(W - 1), 0.0f), (float)(W - 1));
        float yf = fminf(fmaxf((cy + 1.0f) * 0.5f * 255.0f, 0.0f), 255.0f);
        float x0f = fminf(fmaxf(floorf(xf), 0.0f), (float)(W - 2));
        float y0f = fminf(fmaxf(floorf(yf), 0.0f), 254.0f);
        const float wx = xf - x0f;
        const float wy = yf - y0f;
        const int x0 = (int)x0f;
        const int y0 = (int)y0f;
        const float* pl = g_planes + (size_t)POFF[ii] * CCH;
        const int i00 = (y0 * W + x0) * CCH + lane;
        const float v00 = pl[i00];
        const float v01 = pl[i00 + CCH];
        const float v10 = pl[i00 + W * CCH];
        const float v11 = pl[i00 + W * CCH + CCH];
        const float v = v00 * (1.0f - wy) * (1.0f - wx)
                      + v01 * (1.0f - wy) * wx
                      + v10 * wy * (1.0f - wx)
                      + v11 * wy * wx;
        prod *= v;
    }
    out[(size_t)warp * CCH + lane] = prod;
}

extern "C" void kernel_launch(void* const* d_in, const int* in_sizes, int n_in,
                              void* d_out, int out_size) {
    const float* pts = (const float*)d_in[0];
    const float* ts  = (const float*)d_in[1];
    CoefPtrs P;
    for (int i = 0; i < 6; i++) {
        P.yl[i]  = (const float*)d_in[2 + 3 * i];
        P.yha[i] = (const float*)d_in[3 + 3 * i];
        P.yhb[i] = (const float*)d_in[4 + 3 * i];
    }
    float* out = (float*)d_out;
    const int nPts = in_sizes[1];   // timestamps count = N

    dim3 blk(256);
    k_stage1<<<dim3((CCH * 128 * 64 + 255) / 256, 6), blk>>>(P);
    k_stage2<<<dim3((CCH * 128 * 128 + 255) / 256, 6), blk>>>();
    k_stage3<<<dim3((CCH * 256 * 128 + 255) / 256, 6), blk>>>(P);
    k_stage4<<<dim3(256, 6), blk>>>();

    const int totalThreads = nPts * 32;
    k_sample<<<(totalThreads + 255) / 256, 256>>>(pts, ts, out, nPts);
}

// round 7
// speedup vs baseline: 3.3803x; 1.0303x over previous
#include <cuda_runtime.h>
#include <cuda_fp16.h>

// ---------------------------------------------------------------------------
// WavePlaneField: 6 planes reconstructed via 2-level inverse DWT (coif4,
// periodization), bilinear-sampled at N points, channelwise product.
//
// Phase 1 (4 kernels): separable inverse DWT per plane into g_planes[H,W,C]
//   (fp16 storage; fp32 compute). Stage 4 row-tiled via smem, paired-parity
//   (two outputs per thread share all 24 smem operands).
// Phase 2 (1 kernel): warp-per-point sampler, lane = channel, fp16 planes.
// ---------------------------------------------------------------------------

#define CCH 32

// All planes have H=256. W per plane:
__constant__ int c_W[6]    = {256, 256, 64, 256, 64, 64};
__constant__ int c_POFF[6] = {0, 65536, 131072, 147456, 212992, 229376}; // pixel offsets

// coif4 reconstruction filters (24 taps)
__constant__ float REC_LO_C[24] = {
    0.0008923136685823146f, -0.0016294920126017326f, -0.0073461663276420935f,
    0.016068943964776348f, 0.026682300156053072f, -0.08126669968087875f,
    -0.05607731331675481f, 0.41530840703043026f, 0.782238930920499f,
    0.4343860564914685f, -0.06662747426342504f, -0.09622044203398798f,
    0.03933442712333749f, 0.025082261844864097f, -0.015211731527946259f,
    -0.00565828668661072f, 0.003751436157278457f, 0.0012665619292989445f,
    -0.0005890207562443383f, -0.00025997455248771324f, 6.233903446100713e-05f,
    3.1229875865345646e-05f, -3.2596802368833675e-06f, -1.7849850030882614e-06f
};
__constant__ float REC_HI_C[24] = {
    -1.7849850030882614e-06f, 3.2596802368833675e-06f, 3.1229875865345646e-05f,
    -6.233903446100713e-05f, -0.00025997455248771324f, 0.0005890207562443383f,
    0.0012665619292989445f, -0.003751436157278457f, -0.00565828668661072f,
    0.015211731527946259f, 0.025082261844864097f, -0.03933442712333749f,
    -0.09622044203398798f, 0.06662747426342504f, 0.4343860564914685f,
    -0.782238930920499f, 0.41530840703043026f, 0.05607731331675481f,
    -0.08126669968087875f, -0.026682300156053072f, 0.016068943964776348f,
    0.0073461663276420935f, -0.0016294920126017326f, -0.0008923136685823146f
};

// Scratch (static device globals; per-plane strides sized for the largest plane)
#define S_LO1 262144    // C*128*64
#define S_MID 524288    // C*128*128
#define S_LO2 1048576   // C*256*128
__device__ float g_lo1[6 * S_LO1];
__device__ float g_hi1[6 * S_LO1];
__device__ float g_mid[6 * S_MID];
__device__ float g_lo2[6 * S_LO2];
__device__ float g_hi2[6 * S_LO2];
__device__ __half g_planes[245760 * CCH];   // [H,W,C] per plane, concat (fp16)

struct CoefPtrs {
    const float* yl[6];
    const float* yha[6];
    const float* yhb[6];
};

// Stage 1: level-1 H-axis synthesis. in: yl[C,64,w4], yhb[C,3,64,w4]
// out: lo1,hi1 [C,128,w4]
__global__ void k_stage1(CoefPtrs P) {
    const int pl = blockIdx.y;
    const int w4 = c_W[pl] >> 2;
    const int n = CCH * 128 * w4;
    const int tid = blockIdx.x * blockDim.x + threadIdx.x;
    if (tid >= n) return;
    const int x = tid % w4;
    const int i = (tid / w4) & 127;
    const int c = tid / (w4 * 128);
    const int s = i >> 1, p = i & 1;
    const float* yl = P.yl[pl];
    const float* yhb = P.yhb[pl];
    const int bandStride = 64 * w4;
    float lo = 0.f, hi = 0.f;
#pragma unroll
    for (int m = 0; m < 12; m++) {
        int row = s - m; if (row < 0) row += 64;
        const float fl = REC_LO_C[2 * m + p];
        const float fh = REC_HI_C[2 * m + p];
        const int bi = (c * 64 + row) * w4 + x;
        const int b0 = ((c * 3 + 0) * 64 + row) * w4 + x;
        lo += fl * yl[bi] + fh * yhb[b0];
        hi += fl * yhb[b0 + bandStride] + fh * yhb[b0 + 2 * bandStride];
    }
    g_lo1[pl * S_LO1 + tid] = lo;
    g_hi1[pl * S_LO1 + tid] = hi;
}

// Stage 2: level-1 W-axis synthesis. in: lo1,hi1 [C,128,w4] -> mid [C,128,w2]
__global__ void k_stage2() {
    const int pl = blockIdx.y;
    const int w2 = c_W[pl] >> 1;
    const int w4 = w2 >> 1;
    const int n = CCH * 128 * w2;
    const int tid = blockIdx.x * blockDim.x + threadIdx.x;
    if (tid >= n) return;
    const int j = tid % w2;
    const int i = (tid / w2) & 127;
    const int c = tid / (w2 * 128);
    const int s = j >> 1, p = j & 1;
    const int base = pl * S_LO1 + (c * 128 + i) * w4;
    float v = 0.f;
#pragma unroll
    for (int m = 0; m < 12; m++) {
        int col = s - m; if (col < 0) col += w4;
        v += REC_LO_C[2 * m + p] * g_lo1[base + col]
           + REC_HI_C[2 * m + p] * g_hi1[base + col];
    }
    g_mid[pl * S_MID + tid] = v;
}

// Stage 3: level-2 H-axis synthesis. in: mid [C,128,w2], yha [C,3,128,w2]
// out: lo2,hi2 [C,256,w2]
__global__ void k_stage3(CoefPtrs P) {
    const int pl = blockIdx.y;
    const int w2 = c_W[pl] >> 1;
    const int n = CCH * 256 * w2;
    const int tid = blockIdx.x * blockDim.x + threadIdx.x;
    if (tid >= n) return;
    const int x = tid % w2;
    const int i = (tid / w2) & 255;
    const int c = tid / (w2 * 256);
    const int s = i >> 1, p = i & 1;
    const float* yha = P.yha[pl];
    const int bandStride = 128 * w2;
    const int midBase = pl * S_MID;
    float lo = 0.f, hi = 0.f;
#pragma unroll
    for (int m = 0; m < 12; m++) {
        int row = s - m; if (row < 0) row += 128;
        const float fl = REC_LO_C[2 * m + p];
        const float fh = REC_HI_C[2 * m + p];
        const int bi = (c * 128 + row) * w2 + x;
        const int b0 = ((c * 3 + 0) * 128 + row) * w2 + x;
        lo += fl * g_mid[midBase + bi] + fh * yha[b0];
        hi += fl * yha[b0 + bandStride] + fh * yha[b0 + 2 * bandStride];
    }
    g_lo2[pl * S_LO2 + tid] = lo;
    g_hi2[pl * S_LO2 + tid] = hi;
}

// Stage 4 (row-tiled, paired-parity): level-2 W-axis synthesis + transpose to
// [H,W,C] fp16. One block per (plane, y). Each thread computes BOTH parities
// of an output x-pair (x=2s, x=2s+1): the 24 smem operands are identical,
// only the filter phase differs -> halves LDS + address ALU per output.
__global__ void __launch_bounds__(256) k_stage4() {
    const int pl = blockIdx.y;
    const int W = c_W[pl];
    const int w2 = W >> 1;
    const int y = blockIdx.x;

    __shared__ float lo_s[32][129];
    __shared__ float hi_s[32][129];

    const int sh = (w2 == 128) ? 7 : 5;          // log2(w2)
    const int rowBase = pl * S_LO2 + y * w2;     // + c*256*w2 per channel
    for (int t = threadIdx.x; t < 32 * w2; t += 256) {
        const int c = t >> sh;
        const int col = t & (w2 - 1);
        const int gi = rowBase + c * (256 * w2) + col;
        lo_s[c][col] = g_lo2[gi];
        hi_s[c][col] = g_hi2[gi];
    }
    __syncthreads();

    __half* __restrict__ outRow = g_planes + ((size_t)(c_POFF[pl] + y * W)) * CCH;
    const int nPairs = w2 * CCH;                  // one thread -> 2 outputs
    for (int t = threadIdx.x; t < nPairs; t += 256) {
        const int c = t & 31;                     // = lane
        const int s = t >> 5;
        float v0 = 0.f, v1 = 0.f;                 // parity 0 / parity 1
#pragma unroll
        for (int m = 0; m < 12; m++) {
            int col = s - m; if (col < 0) col += w2;
            const float lv = lo_s[c][col];
            const float hv = hi_s[c][col];
            v0 += REC_LO_C[2 * m]     * lv + REC_HI_C[2 * m]     * hv;
            v1 += REC_LO_C[2 * m + 1] * lv + REC_HI_C[2 * m + 1] * hv;
        }
        outRow[(2 * s) * CCH + c]     = __float2half(v0);
        outRow[(2 * s + 1) * CCH + c] = __float2half(v1);
    }
}

// Phase 2: warp per point, lane = channel. fp16 plane reads (64B/warp/corner).
__global__ void __launch_bounds__(256) k_sample(const float* __restrict__ pts,
                                                const float* __restrict__ ts,
                                                float* __restrict__ out,
                                                int nPts) {
    const int warp = (blockIdx.x * blockDim.x + threadIdx.x) >> 5;
    const int lane = threadIdx.x & 31;
    if (warp >= nPts) return;

    const float px = pts[warp * 3 + 0];
    const float py = pts[warp * 3 + 1];
    const float pz = pts[warp * 3 + 2];
    const float tt = ts[warp];
    // pts_n = (pts - B)*(2/(-2B)) - 1 = -pts/B
    const float inv = -1.0f / 1.3f;
    float p4[4];
    p4[0] = px * inv;
    p4[1] = py * inv;
    p4[2] = pz * inv;
    p4[3] = tt * 2.0f - 1.0f;

    constexpr int QIDX[6] = {0, 0, 3, 1, 3, 3};
    constexpr int RIDX[6] = {1, 2, 0, 2, 1, 2};
    constexpr int PW[6]   = {256, 256, 64, 256, 64, 64};
    constexpr int POFF[6] = {0, 65536, 131072, 147456, 212992, 229376};

    float prod = 1.0f;
#pragma unroll
    for (int ii = 0; ii < 6; ii++) {
        const int W = PW[ii];
        const float cx = p4[QIDX[ii]];
        const float cy = p4[RIDX[ii]];
        float xf = fminf(fmaxf((cx + 1.0f) * 0.5f * (float)(W - 1), 0.0f), (float)(W - 1));
        float yf = fminf(fmaxf((cy + 1.0f) * 0.5f * 255.0f, 0.0f), 255.0f);
        float x0f = fminf(fmaxf(floorf(xf), 0.0f), (float)(W - 2));
        float y0f = fminf(fmaxf(floorf(yf), 0.0f), 254.0f);
        const float wx = xf - x0f;
        const float wy = yf - y0f;
        const int x0 = (int)x0f;
        const int y0 = (int)y0f;
        const __half* pl = g_planes + (size_t)POFF[ii] * CCH;
        const int i00 = (y0 * W + x0) * CCH + lane;
        const float v00 = __half2float(pl[i00]);
        const float v01 = __half2float(pl[i00 + CCH]);
        const float v10 = __half2float(pl[i00 + W * CCH]);
        const float v11 = __half2float(pl[i00 + W * CCH + CCH]);
        const float v = v00 * (1.0f - wy) * (1.0f - wx)
                      + v01 * (1.0f - wy) * wx
                      + v10 * wy * (1.0f - wx)
                      + v11 * wy * wx;
        prod *= v;
    }
    out[(size_t)warp * CCH + lane] = prod;
}

extern "C" void kernel_launch(void* const* d_in, const int* in_sizes, int n_in,
                              void* d_out, int out_size) {
    const float* pts = (const float*)d_in[0];
    const float* ts  = (const float*)d_in[1];
    CoefPtrs P;
    for (int i = 0; i < 6; i++) {
        P.yl[i]  = (const float*)d_in[2 + 3 * i];
        P.yha[i] = (const float*)d_in[3 + 3 * i];
        P.yhb[i] = (const float*)d_in[4 + 3 * i];
    }
    float* out = (float*)d_out;
    const int nPts = in_sizes[1];   // timestamps count = N

    dim3 blk(256);
    k_stage1<<<dim3((CCH * 128 * 64 + 255) / 256, 6), blk>>>(P);
    k_stage2<<<dim3((CCH * 128 * 128 + 255) / 256, 6), blk>>>();
    k_stage3<<<dim3((CCH * 256 * 128 + 255) / 256, 6), blk>>>(P);
    k_stage4<<<dim3(256, 6), blk>>>();

    const int totalThreads = nPts * 32;
    k_sample<<<(totalThreads + 255) / 256, 256>>>(pts, ts, out, nPts);
}